// round 11
// baseline (speedup 1.0000x reference)
#include <cuda_runtime.h>
#include <cuda_bf16.h>

#define L  48
#define NB 132     // grid size; <=148 SMs -> all blocks co-resident (1 wave)

// ---- scratch (device globals; no allocations) ----
__device__ float g_qkp[2][L * 256];   // split-K partials: [0,128)=q, [128,256)=k
__device__ float g_rootp[2][L * 256]; // split-K partials of X @ W_root
__device__ float g_attn[L * L];
__device__ float g_h[L * 256];

// grid barrier (count returns to 0 each barrier; gen read-before-arrive)
__device__ int g_bar_count;
__device__ volatile int g_bar_gen;

// local t = sp_i*4 + sp_j*2 + dir  ->  global etype = 96*sp_i + 2*sp_j + dir
__constant__ int c_etype[8] = {0, 1, 2, 3, 96, 97, 98, 99};

__device__ __forceinline__ float ftanh(float x) {
    float y; asm("tanh.approx.f32 %0, %1;" : "=f"(y) : "f"(x)); return y;
}

__device__ __forceinline__ void gsync() {
    __syncthreads();
    if (threadIdx.x == 0) {
        __threadfence();                       // release
        int gen = g_bar_gen;                   // read BEFORE arriving
        if (atomicAdd(&g_bar_count, 1) == NB - 1) {
            g_bar_count = 0;
            __threadfence();
            g_bar_gen = gen + 1;
        } else {
            while (g_bar_gen == gen) { }
        }
        __threadfence();                       // acquire
    }
    __syncthreads();
}

__global__ void __launch_bounds__(256)
fused(const float* __restrict__ X,      const int*   __restrict__ speaker,
      const float* __restrict__ Wq,     const float* __restrict__ Wk,
      const float* __restrict__ v,      const float* __restrict__ Wrel,
      const float* __restrict__ Wr,     const float* __restrict__ b_rgcn,
      const float* __restrict__ Wnbr,   const float* __restrict__ Wself,
      const float* __restrict__ bg,     float*       __restrict__ out) {
    __shared__ float smem[6784];               // 26.5 KB, re-carved per phase
    int bid = blockIdx.x, tid = threadIdx.x;

    // ===== P1: [q|k|root] = X @ [Wq|Wk|Wroot], split-K partials =============
    // 128 blocks: 16 rowtiles(3) x 4 colslices(128) x 2 k-halves(128).
    if (bid < 128) {
        int rt = bid & 15, cs = (bid >> 4) & 3, ko = bid >> 6;
        float* xs  = smem;                     // [3][128]
        float* red = smem + 384;               // [128][3]
        for (int idx = tid; idx < 384; idx += 256) {
            int rr = idx >> 7, dd = idx & 127;
            xs[idx] = X[(rt * 3 + rr) * 256 + ko * 128 + dd];
        }
        __syncthreads();
        int cl = tid & 127, ki = tid >> 7;
        int c  = cs * 128 + cl;
        const float* Wb; int stride;
        if (c < 128)      { Wb = Wq + c;         stride = 128; }
        else if (c < 256) { Wb = Wk + (c - 128); stride = 128; }
        else              { Wb = Wr + (c - 256); stride = 256; }
        Wb += (size_t)(ko * 128 + ki * 64) * stride;
        const float *x0 = &xs[ki * 64], *x1 = &xs[128 + ki * 64], *x2 = &xs[256 + ki * 64];
        float a0 = 0.f, a1 = 0.f, a2 = 0.f;
#pragma unroll 8
        for (int d = 0; d < 64; d++) {
            float w = Wb[(size_t)d * stride];
            a0 = fmaf(x0[d], w, a0); a1 = fmaf(x1[d], w, a1); a2 = fmaf(x2[d], w, a2);
        }
        if (ki == 1) { red[cl * 3] = a0; red[cl * 3 + 1] = a1; red[cl * 3 + 2] = a2; }
        __syncthreads();
        if (ki == 0) {
            a0 += red[cl * 3]; a1 += red[cl * 3 + 1]; a2 += red[cl * 3 + 2];
            float* dst = (c < 256) ? &g_qkp[ko][0] : &g_rootp[ko][0];
            int cc = (c < 256) ? c : (c - 256);
            dst[(rt * 3 + 0) * 256 + cc] = a0;
            dst[(rt * 3 + 1) * 256 + cc] = a1;
            dst[(rt * 3 + 2) * 256 + cc] = a2;
        }
    }
    gsync();

    // ===== P2: attention softmax (blocks 0-47)  +  h init (blocks 48-95) ===
    if (bid < 48) {
        float* qs  = smem;            // 128
        float* vs  = smem + 128;      // 128
        float* ks  = smem + 256;      // 48*129
        float* sc  = smem + 6448;     // 48
        float* sp4 = smem + 6496;     // 192
        float* se  = smem + 6688;     // 48
        int i = bid;
        if (tid < 128) {
            qs[tid] = g_qkp[0][i * 256 + tid] + g_qkp[1][i * 256 + tid];
            vs[tid] = v[tid];
        }
        for (int idx = tid; idx < 48 * 128; idx += 256) {
            int u = idx >> 7, a = idx & 127;
            ks[u * 129 + a] = g_qkp[0][u * 256 + 128 + a]
                            + g_qkp[1][u * 256 + 128 + a];
        }
        __syncthreads();
        int s = tid >> 6, u = tid & 63;
        float ps = 0.f;
        if (u < 48) {
            const float *kk = &ks[u * 129 + s * 32], *qq = &qs[s * 32], *vv = &vs[s * 32];
#pragma unroll
            for (int a = 0; a < 32; a++) ps += vv[a] * ftanh(qq[a] + kk[a]);
            sp4[s * 48 + u] = ps;
        }
        __syncthreads();
        if (tid < 48)
            sc[tid] = sp4[tid] + sp4[48 + tid] + sp4[96 + tid] + sp4[144 + tid];
        __syncthreads();
        float e = 0.f;
        if (tid < 48) {
            float mx = sc[0];
#pragma unroll 8
            for (int j = 1; j < 48; j++) mx = fmaxf(mx, sc[j]);
            e = __expf(sc[tid] - mx);
            se[tid] = e;
        }
        __syncthreads();
        if (tid < 48) {
            float sum = 0.f;
#pragma unroll 8
            for (int j = 0; j < 48; j++) sum += se[j];
            g_attn[i * 48 + tid] = e / sum;
        }
    } else if (bid < 96) {
        int o = (bid - 48) * 256 + tid;        // h init = root + b_rgcn
        g_h[o] = g_rootp[0][o] + g_rootp[1][o] + b_rgcn[o & 255];
    }
    gsync();

    // ===== P4: h += Z_t @ W_t, Z built inline (no global Z round-trip) =====
    // 128 blocks: 8 types x 8 ksplit(32) x 2 rowtiles(24).
    // Blocks 128-131: init out = b_gcn.
    if (bid < 128) {
        int t  = bid & 7, ks = (bid >> 3) & 7, rt = bid >> 6;
        int tb   = (t >> 1) & 1;               // sp_j bit of this type
        int tsi  = t >> 2;                     // sp_i bit
        int dirb = t & 1;                      // direction bit
        int row0 = rt * 24, d0 = ks * 32;
        float* xs = smem;                      // [48][32]  X slice
        float* as = smem + 1536;               // [48][24]  attn cols
        float* zs = smem + 2688;               // [24][32]  Z slice
        int*   sp = (int*)(smem + 3456);       // [48]
        for (int idx = tid; idx < 1536; idx += 256) {
            int i = idx >> 5, dd = idx & 31;
            xs[idx] = X[i * 256 + d0 + dd];
        }
        for (int idx = tid; idx < 1152; idx += 256) {
            int i = idx / 24, jj = idx % 24;
            as[idx] = g_attn[i * 48 + row0 + jj];
        }
        if (tid < 48) sp[tid] = speaker[tid];
        __syncthreads();

        // Z compute: thread (jgroup=tid>>5, d=tid&31) -> 3 j's
        {
            int jg = tid >> 5, d = tid & 31;
#pragma unroll
            for (int r = 0; r < 3; r++) {
                int jj = jg * 3 + r, j = row0 + jj;
                float acc = 0.f;
#pragma unroll 8
                for (int i = 0; i < 48; i++) {
                    int dir = (i < j) ? 0 : 1;
                    bool inc = (sp[i] == tsi) && (dir == dirb);
                    acc += inc ? as[i * 24 + jj] * xs[i * 32 + d] : 0.f;
                }
                zs[jj * 32 + d] = acc;
            }
        }
        __syncthreads();

        // GEMM: thread micro-tile 6 rows x 4 cols, K=32, float4 W loads
        int cq = (tid & 63) * 4, rg = tid >> 6;
        const float* W = Wrel + (size_t)c_etype[t] * 65536 + (size_t)d0 * 256 + cq;
        const float* z = &zs[rg * 6 * 32];
        float4 acc[6] = {{0,0,0,0},{0,0,0,0},{0,0,0,0},{0,0,0,0},{0,0,0,0},{0,0,0,0}};
#pragma unroll 4
        for (int d = 0; d < 32; d++) {
            float4 w = *(const float4*)&W[(size_t)d * 256];
#pragma unroll
            for (int r = 0; r < 6; r++) {
                float zv = z[r * 32 + d];
                acc[r].x = fmaf(zv, w.x, acc[r].x);
                acc[r].y = fmaf(zv, w.y, acc[r].y);
                acc[r].z = fmaf(zv, w.z, acc[r].z);
                acc[r].w = fmaf(zv, w.w, acc[r].w);
            }
        }
        int lr = rg * 6;
#pragma unroll
        for (int r = 0; r < 6; r++) {
            if (sp[row0 + lr + r] == tb) {
                float* p = &g_h[(row0 + lr + r) * 256 + cq];
                atomicAdd(p + 0, acc[r].x); atomicAdd(p + 1, acc[r].y);
                atomicAdd(p + 2, acc[r].z); atomicAdd(p + 3, acc[r].w);
            }
        }
    } else {
        int base = (bid - 128) * 3072;         // init out = bias
        float b = bg[tid];
#pragma unroll
        for (int k = 0; k < 12; k++)
            out[base + k * 256 + tid] = b;
    }
    gsync();

    // ===== P5: out += h @ W_self (k-split REDG)  +  broadcast T ============
    if (bid < 128) {
        // 16 rowtiles(3) x 2 colhalves(128) x 4 ksplit(64); inner ki splits 32.
        int rt = bid & 15, cs = (bid >> 4) & 1, ks = bid >> 5;
        float* hs  = smem;                     // [3][64]
        float* red = smem + 192;               // [128][3]
        int r0 = rt * 3;
        for (int idx = tid; idx < 192; idx += 256) {
            int rr = idx >> 6, dd = idx & 63;
            hs[idx] = g_h[(r0 + rr) * 256 + ks * 64 + dd];
        }
        __syncthreads();
        int cl = tid & 127, ki = tid >> 7;
        int c  = cs * 128 + cl;
        const float* Wb = Wself + (size_t)(ks * 64 + ki * 32) * 256 + c;
        const float *h0 = &hs[ki * 32], *h1 = &hs[64 + ki * 32], *h2 = &hs[128 + ki * 32];
        float a0 = 0.f, a1 = 0.f, a2 = 0.f;
#pragma unroll 8
        for (int d = 0; d < 32; d++) {
            float w = Wb[(size_t)d * 256];
            a0 = fmaf(h0[d], w, a0); a1 = fmaf(h1[d], w, a1); a2 = fmaf(h2[d], w, a2);
        }
        if (ki == 1) { red[cl * 3] = a0; red[cl * 3 + 1] = a1; red[cl * 3 + 2] = a2; }
        __syncthreads();
        if (ki == 0) {
            atomicAdd(&out[(r0 + 0) * 256 + c], a0 + red[cl * 3]);
            atomicAdd(&out[(r0 + 1) * 256 + c], a1 + red[cl * 3 + 1]);
            atomicAdd(&out[(r0 + 2) * 256 + c], a2 + red[cl * 3 + 2]);
        }
    } else {
        // blocks 128..131: T k-chunk partial, scatter-added to all 48 rows
        int b = bid - 128;
        float* Ssc = smem;                     // [4][64]
        float* Sc  = smem + 256;               // [64]
        int dd = tid & 63, jg = tid >> 6;
        float s = 0.f;
#pragma unroll
        for (int j = jg * 12; j < jg * 12 + 12; j++)
            s += g_h[j * 256 + b * 64 + dd];
        Ssc[jg * 64 + dd] = s;
        __syncthreads();
        if (tid < 64) Sc[tid] = Ssc[tid] + Ssc[64 + tid] + Ssc[128 + tid] + Ssc[192 + tid];
        __syncthreads();
        float t = 0.f;
#pragma unroll 8
        for (int d = 0; d < 64; d++)
            t = fmaf(Sc[d], Wnbr[(size_t)(b * 64 + d) * 256 + tid], t);
#pragma unroll 8
        for (int j = 0; j < 48; j++)
            atomicAdd(&out[j * 256 + tid], t);
    }
}

extern "C" void kernel_launch(void* const* d_in, const int* in_sizes, int n_in,
                              void* d_out, int out_size) {
    const float* X      = (const float*)d_in[0];
    const int*   spk    = (const int*)  d_in[1];
    const float* Wq     = (const float*)d_in[2];
    const float* Wk     = (const float*)d_in[3];
    const float* v      = (const float*)d_in[4];
    const float* Wrel   = (const float*)d_in[5];
    const float* Wroot  = (const float*)d_in[6];
    const float* b_rgcn = (const float*)d_in[7];
    const float* Wnbr   = (const float*)d_in[8];
    const float* Wself  = (const float*)d_in[9];
    const float* b_gcn  = (const float*)d_in[10];
    float* out = (float*)d_out;

    fused<<<NB, 256>>>(X, spk, Wq, Wk, v, Wrel, Wroot, b_rgcn, Wnbr, Wself,
                       b_gcn, out);
}

// round 12
// speedup vs baseline: 1.2169x; 1.2169x over previous
#include <cuda_runtime.h>
#include <cuda_bf16.h>

#define L  48
#define NB 264     // 2 blocks/SM co-resident (264 < 2*148) -> single wave

// ---- scratch (device globals; no allocations) ----
__device__ float g_qkp[2][L * 256];   // split-K partials: [0,128)=q, [128,256)=k
__device__ float g_rootp[2][L * 256]; // split-K partials of X @ W_root
__device__ float g_attn[L * L];
__device__ float g_h[L * 256];

// grid barrier (count returns to 0 each barrier; gen read-before-arrive)
__device__ int g_bar_count;
__device__ volatile int g_bar_gen;

// local t = sp_i*4 + sp_j*2 + dir  ->  global etype = 96*sp_i + 2*sp_j + dir
__constant__ int c_etype[8] = {0, 1, 2, 3, 96, 97, 98, 99};

__device__ __forceinline__ float ftanh(float x) {
    float y; asm("tanh.approx.f32 %0, %1;" : "=f"(y) : "f"(x)); return y;
}

__device__ __forceinline__ void gsync() {
    __syncthreads();
    if (threadIdx.x == 0) {
        __threadfence();                       // release
        int gen = g_bar_gen;                   // read BEFORE arriving
        if (atomicAdd(&g_bar_count, 1) == NB - 1) {
            g_bar_count = 0;
            __threadfence();
            g_bar_gen = gen + 1;
        } else {
            while (g_bar_gen == gen) { }
        }
        __threadfence();                       // acquire
    }
    __syncthreads();
}

__global__ void __launch_bounds__(256, 2)
fused(const float* __restrict__ X,      const int*   __restrict__ speaker,
      const float* __restrict__ Wq,     const float* __restrict__ Wk,
      const float* __restrict__ v,      const float* __restrict__ Wrel,
      const float* __restrict__ Wr,     const float* __restrict__ b_rgcn,
      const float* __restrict__ Wnbr,   const float* __restrict__ Wself,
      const float* __restrict__ bg,     float*       __restrict__ out) {
    __shared__ float smem[6784];               // 26.5 KB, re-carved per phase
    int bid = blockIdx.x, tid = threadIdx.x;

    // ===== P1: [q|k|root] = X @ [Wq|Wk|Wroot], split-K partials =============
    // 256 blocks: 16 rowtiles(3) x 8 colslices(64) x 2 k-halves(128).
    // Inner: 4-way ki split of 128 -> 32 W-loads per thread.
    if (bid < 256) {
        int rt = bid & 15, cs = (bid >> 4) & 7, ko = bid >> 7;
        float* xs  = smem;                     // [3][128]
        float* red = smem + 384;               // [3][64*3]
        for (int idx = tid; idx < 384; idx += 256) {
            int rr = idx >> 7, dd = idx & 127;
            xs[idx] = X[(rt * 3 + rr) * 256 + ko * 128 + dd];
        }
        __syncthreads();
        int cl = tid & 63, ki = tid >> 6;      // 64 cols x 4 k-chunks(32)
        int c  = cs * 64 + cl;
        const float* Wb; int stride;
        if (c < 128)      { Wb = Wq + c;         stride = 128; }
        else if (c < 256) { Wb = Wk + (c - 128); stride = 128; }
        else              { Wb = Wr + (c - 256); stride = 256; }
        Wb += (size_t)(ko * 128 + ki * 32) * stride;
        const float* xk = &xs[ki * 32];
        float a0 = 0.f, a1 = 0.f, a2 = 0.f;
#pragma unroll
        for (int d = 0; d < 32; d++) {
            float w = Wb[(size_t)d * stride];
            a0 = fmaf(xk[d],       w, a0);
            a1 = fmaf(xk[128 + d], w, a1);
            a2 = fmaf(xk[256 + d], w, a2);
        }
        if (ki > 0) {
            float* r = &red[(ki - 1) * 192 + cl * 3];
            r[0] = a0; r[1] = a1; r[2] = a2;
        }
        __syncthreads();
        if (ki == 0) {
            const float *r1 = &red[cl * 3], *r2 = &red[192 + cl * 3], *r3 = &red[384 + cl * 3];
            a0 += r1[0] + r2[0] + r3[0];
            a1 += r1[1] + r2[1] + r3[1];
            a2 += r1[2] + r2[2] + r3[2];
            float* dst = (c < 256) ? &g_qkp[ko][0] : &g_rootp[ko][0];
            int cc = (c < 256) ? c : (c - 256);
            dst[(rt * 3 + 0) * 256 + cc] = a0;
            dst[(rt * 3 + 1) * 256 + cc] = a1;
            dst[(rt * 3 + 2) * 256 + cc] = a2;
        }
    }
    gsync();

    // ===== P2: attention softmax (blocks 0-47)  +  h init (blocks 48-95) ===
    if (bid < 48) {
        float* qs  = smem;            // 128
        float* vs  = smem + 128;      // 128
        float* ks  = smem + 256;      // 48*129
        float* sc  = smem + 6448;     // 48
        float* sp4 = smem + 6496;     // 192
        float* se  = smem + 6688;     // 48
        int i = bid;
        if (tid < 128) {
            qs[tid] = g_qkp[0][i * 256 + tid] + g_qkp[1][i * 256 + tid];
            vs[tid] = v[tid];
        }
        for (int idx = tid; idx < 48 * 128; idx += 256) {
            int u = idx >> 7, a = idx & 127;
            ks[u * 129 + a] = g_qkp[0][u * 256 + 128 + a]
                            + g_qkp[1][u * 256 + 128 + a];
        }
        __syncthreads();
        int s = tid >> 6, u = tid & 63;
        float ps = 0.f;
        if (u < 48) {
            const float *kk = &ks[u * 129 + s * 32], *qq = &qs[s * 32], *vv = &vs[s * 32];
#pragma unroll
            for (int a = 0; a < 32; a++) ps += vv[a] * ftanh(qq[a] + kk[a]);
            sp4[s * 48 + u] = ps;
        }
        __syncthreads();
        if (tid < 48)
            sc[tid] = sp4[tid] + sp4[48 + tid] + sp4[96 + tid] + sp4[144 + tid];
        __syncthreads();
        float e = 0.f;
        if (tid < 48) {
            float mx = sc[0];
#pragma unroll 8
            for (int j = 1; j < 48; j++) mx = fmaxf(mx, sc[j]);
            e = __expf(sc[tid] - mx);
            se[tid] = e;
        }
        __syncthreads();
        if (tid < 48) {
            float sum = 0.f;
#pragma unroll 8
            for (int j = 0; j < 48; j++) sum += se[j];
            g_attn[i * 48 + tid] = e / sum;
        }
    } else if (bid < 96) {
        int o = (bid - 48) * 256 + tid;        // h init = root + b_rgcn
        g_h[o] = g_rootp[0][o] + g_rootp[1][o] + b_rgcn[tid];
    }
    gsync();

    // ===== P4: h += Z_t @ W_t, Z built inline ==============================
    // 256 blocks: 8 types x 8 ksplit(32) x 4 rowtiles(12).
    // Blocks 256-259: init out = b_gcn.
    if (bid < 256) {
        int t  = bid & 7, ks = (bid >> 3) & 7, rt = bid >> 6;
        int tb   = (t >> 1) & 1;               // sp_j bit of this type
        int tsi  = t >> 2;                     // sp_i bit
        int dirb = t & 1;                      // direction bit
        int row0 = rt * 12, d0 = ks * 32;
        float* xs = smem;                      // [48][32]  X slice
        float* as = smem + 1536;               // [48][12]  attn cols
        float* zs = smem + 2112;               // [12][32]  Z slice
        int*   sp = (int*)(smem + 2496);       // [48]
        for (int idx = tid; idx < 1536; idx += 256) {
            int i = idx >> 5, dd = idx & 31;
            xs[idx] = X[i * 256 + d0 + dd];
        }
        for (int idx = tid; idx < 576; idx += 256) {
            int i = idx / 12, jj = idx % 12;
            if (idx < 576) as[idx] = g_attn[i * 48 + row0 + jj];
        }
        if (tid < 48) sp[tid] = speaker[tid];
        __syncthreads();

        // Z compute: 384 elements, <=2 per thread
        for (int idx = tid; idx < 384; idx += 256) {
            int jj = idx >> 5, d = idx & 31;
            int j = row0 + jj;
            float acc = 0.f;
#pragma unroll 8
            for (int i = 0; i < 48; i++) {
                int dir = (i < j) ? 0 : 1;
                bool inc = (sp[i] == tsi) && (dir == dirb);
                acc += inc ? as[i * 12 + jj] * xs[i * 32 + d] : 0.f;
            }
            zs[jj * 32 + d] = acc;
        }
        __syncthreads();

        // GEMM: thread micro-tile 3 rows x 4 cols, K=32, float4 W loads
        int cq = (tid & 63) * 4, rg = tid >> 6;
        const float* W = Wrel + (size_t)c_etype[t] * 65536 + (size_t)d0 * 256 + cq;
        const float* z = &zs[rg * 3 * 32];
        float4 a0 = {0,0,0,0}, a1 = {0,0,0,0}, a2 = {0,0,0,0};
#pragma unroll 8
        for (int d = 0; d < 32; d++) {
            float4 w = *(const float4*)&W[(size_t)d * 256];
            float v0 = z[d], v1 = z[32 + d], v2 = z[64 + d];
            a0.x = fmaf(v0, w.x, a0.x); a0.y = fmaf(v0, w.y, a0.y);
            a0.z = fmaf(v0, w.z, a0.z); a0.w = fmaf(v0, w.w, a0.w);
            a1.x = fmaf(v1, w.x, a1.x); a1.y = fmaf(v1, w.y, a1.y);
            a1.z = fmaf(v1, w.z, a1.z); a1.w = fmaf(v1, w.w, a1.w);
            a2.x = fmaf(v2, w.x, a2.x); a2.y = fmaf(v2, w.y, a2.y);
            a2.z = fmaf(v2, w.z, a2.z); a2.w = fmaf(v2, w.w, a2.w);
        }
        int lr = rg * 3;
        if (sp[row0 + lr + 0] == tb) {
            float* p = &g_h[(row0 + lr + 0) * 256 + cq];
            atomicAdd(p+0, a0.x); atomicAdd(p+1, a0.y);
            atomicAdd(p+2, a0.z); atomicAdd(p+3, a0.w);
        }
        if (sp[row0 + lr + 1] == tb) {
            float* p = &g_h[(row0 + lr + 1) * 256 + cq];
            atomicAdd(p+0, a1.x); atomicAdd(p+1, a1.y);
            atomicAdd(p+2, a1.z); atomicAdd(p+3, a1.w);
        }
        if (sp[row0 + lr + 2] == tb) {
            float* p = &g_h[(row0 + lr + 2) * 256 + cq];
            atomicAdd(p+0, a2.x); atomicAdd(p+1, a2.y);
            atomicAdd(p+2, a2.z); atomicAdd(p+3, a2.w);
        }
    } else if (bid < 260) {
        int base = (bid - 256) * 3072;         // init out = bias
        float b = bg[tid];
#pragma unroll
        for (int k = 0; k < 12; k++)
            out[base + k * 256 + tid] = b;
    }
    gsync();

    // ===== P5: out += h @ W_self (k-split REDG)  +  broadcast T ============
    if (bid < 256) {
        // 16 rowtiles(3) x 2 colhalves(128) x 8 ksplit(32); inner ki splits 16.
        int rt = bid & 15, cs = (bid >> 4) & 1, ks = bid >> 5;
        float* hs  = smem;                     // [3][32]
        float* red = smem + 96;                // [128][3]
        int r0 = rt * 3;
        for (int idx = tid; idx < 96; idx += 256) {
            int rr = idx >> 5, dd = idx & 31;
            hs[idx] = g_h[(r0 + rr) * 256 + ks * 32 + dd];
        }
        __syncthreads();
        int cl = tid & 127, ki = tid >> 7;
        int c  = cs * 128 + cl;
        const float* Wb = Wself + (size_t)(ks * 32 + ki * 16) * 256 + c;
        const float *h0 = &hs[ki * 16], *h1 = &hs[32 + ki * 16], *h2 = &hs[64 + ki * 16];
        float a0 = 0.f, a1 = 0.f, a2 = 0.f;
#pragma unroll
        for (int d = 0; d < 16; d++) {
            float w = Wb[(size_t)d * 256];
            a0 = fmaf(h0[d], w, a0); a1 = fmaf(h1[d], w, a1); a2 = fmaf(h2[d], w, a2);
        }
        if (ki == 1) { red[cl * 3] = a0; red[cl * 3 + 1] = a1; red[cl * 3 + 2] = a2; }
        __syncthreads();
        if (ki == 0) {
            atomicAdd(&out[(r0 + 0) * 256 + c], a0 + red[cl * 3]);
            atomicAdd(&out[(r0 + 1) * 256 + c], a1 + red[cl * 3 + 1]);
            atomicAdd(&out[(r0 + 2) * 256 + c], a2 + red[cl * 3 + 2]);
        }
    } else if (bid < 260) {
        // blocks 256..259: T k-chunk partial, scatter-added to all 48 rows
        int b = bid - 256;
        float* Ssc = smem;                     // [4][64]
        float* Sc  = smem + 256;               // [64]
        int dd = tid & 63, jg = tid >> 6;
        float s = 0.f;
#pragma unroll
        for (int j = jg * 12; j < jg * 12 + 12; j++)
            s += g_h[j * 256 + b * 64 + dd];
        Ssc[jg * 64 + dd] = s;
        __syncthreads();
        if (tid < 64) Sc[tid] = Ssc[tid] + Ssc[64 + tid] + Ssc[128 + tid] + Ssc[192 + tid];
        __syncthreads();
        float t = 0.f;
#pragma unroll 8
        for (int d = 0; d < 64; d++)
            t = fmaf(Sc[d], Wnbr[(size_t)(b * 64 + d) * 256 + tid], t);
#pragma unroll 8
        for (int j = 0; j < 48; j++)
            atomicAdd(&out[j * 256 + tid], t);
    }
}

extern "C" void kernel_launch(void* const* d_in, const int* in_sizes, int n_in,
                              void* d_out, int out_size) {
    const float* X      = (const float*)d_in[0];
    const int*   spk    = (const int*)  d_in[1];
    const float* Wq     = (const float*)d_in[2];
    const float* Wk     = (const float*)d_in[3];
    const float* v      = (const float*)d_in[4];
    const float* Wrel   = (const float*)d_in[5];
    const float* Wroot  = (const float*)d_in[6];
    const float* b_rgcn = (const float*)d_in[7];
    const float* Wnbr   = (const float*)d_in[8];
    const float* Wself  = (const float*)d_in[9];
    const float* b_gcn  = (const float*)d_in[10];
    float* out = (float*)d_out;

    fused<<<NB, 256>>>(X, spk, Wq, Wk, v, Wrel, Wroot, b_rgcn, Wnbr, Wself,
                       b_gcn, out);
}

// round 14
// speedup vs baseline: 1.3117x; 1.0779x over previous
#include <cuda_runtime.h>
#include <cuda_bf16.h>

#define L  48
#define NB 396     // 3 blocks/SM co-resident (396 <= 3*148) -> single wave

// ---- scratch (device globals; no allocations) ----
__device__ float g_qkp[2][L * 256];   // split-K partials: [0,128)=q, [128,256)=k
__device__ float g_rootp[2][L * 256]; // split-K partials of X @ W_root
__device__ float g_attn[L * L];
__device__ float g_h[L * 256];

// grid barrier (count returns to 0 each barrier; gen read-before-arrive)
__device__ int g_bar_count;
__device__ volatile int g_bar_gen;

// local t = sp_i*4 + sp_j*2 + dir  ->  global etype = 96*sp_i + 2*sp_j + dir
__constant__ int c_etype[8] = {0, 1, 2, 3, 96, 97, 98, 99};

__device__ __forceinline__ float ftanh(float x) {
    float y; asm("tanh.approx.f32 %0, %1;" : "=f"(y) : "f"(x)); return y;
}

__device__ __forceinline__ void gsync() {
    __syncthreads();
    if (threadIdx.x == 0) {
        __threadfence();                       // release
        int gen = g_bar_gen;                   // read BEFORE arriving
        if (atomicAdd(&g_bar_count, 1) == NB - 1) {
            g_bar_count = 0;
            __threadfence();
            g_bar_gen = gen + 1;
        } else {
            while (g_bar_gen == gen) { }
        }
        __threadfence();                       // acquire
    }
    __syncthreads();
}

__global__ void __launch_bounds__(256, 3)
fused(const float* __restrict__ X,      const int*   __restrict__ speaker,
      const float* __restrict__ Wq,     const float* __restrict__ Wk,
      const float* __restrict__ v,      const float* __restrict__ Wrel,
      const float* __restrict__ Wr,     const float* __restrict__ b_rgcn,
      const float* __restrict__ Wnbr,   const float* __restrict__ Wself,
      const float* __restrict__ bg,     float*       __restrict__ out) {
    __shared__ float smem[2304];               // 9 KB, re-carved per phase
    int bid = blockIdx.x, tid = threadIdx.x;

    // ===== P1: [q|k|root] = X @ [Wq|Wk|Wroot], split-K partials =============
    // 384 blocks: 12 rowtiles(4) x 16 colslices(32) x 2 k-outer(128).
    // Thread: 32 cols x 8 ki-chunks(16) -> 16 W loads, 4 rows.
    if (bid < 384) {
        int rt = bid >> 5, cs = (bid >> 1) & 15, ko = bid & 1;
        int r0 = rt * 4;
        float* xs  = smem;                     // [4][128]
        float* red = smem + 512;               // [7][4][32]
        for (int idx = tid; idx < 512; idx += 256) {
            int rr = idx >> 7, dd = idx & 127;
            xs[idx] = X[(r0 + rr) * 256 + ko * 128 + dd];
        }
        __syncthreads();
        int cl = tid & 31, ki = tid >> 5;      // ki in [0,8)
        int c  = cs * 32 + cl;
        const float* Wb; int stride;
        if (c < 128)      { Wb = Wq + c;         stride = 128; }
        else if (c < 256) { Wb = Wk + (c - 128); stride = 128; }
        else              { Wb = Wr + (c - 256); stride = 256; }
        Wb += (size_t)(ko * 128 + ki * 16) * stride;
        const float* xk = &xs[ki * 16];
        float a0 = 0.f, a1 = 0.f, a2 = 0.f, a3 = 0.f;
#pragma unroll
        for (int d = 0; d < 16; d++) {
            float w = Wb[(size_t)d * stride];
            a0 = fmaf(xk[d],       w, a0);
            a1 = fmaf(xk[128 + d], w, a1);
            a2 = fmaf(xk[256 + d], w, a2);
            a3 = fmaf(xk[384 + d], w, a3);
        }
        if (ki > 0) {
            float* r = &red[(ki - 1) * 128];
            r[0 * 32 + cl] = a0; r[1 * 32 + cl] = a1;
            r[2 * 32 + cl] = a2; r[3 * 32 + cl] = a3;
        }
        __syncthreads();
        if (ki == 0) {
#pragma unroll
            for (int p = 0; p < 7; p++) {
                const float* r = &red[p * 128];
                a0 += r[cl]; a1 += r[32 + cl]; a2 += r[64 + cl]; a3 += r[96 + cl];
            }
            float* dst = (c < 256) ? &g_qkp[ko][0] : &g_rootp[ko][0];
            int cc = (c < 256) ? c : (c - 256);
            dst[(r0 + 0) * 256 + cc] = a0;
            dst[(r0 + 1) * 256 + cc] = a1;
            dst[(r0 + 2) * 256 + cc] = a2;
            dst[(r0 + 3) * 256 + cc] = a3;
        }
    }
    gsync();

    // ===== P2: attention (0-47) + h init (48-95) + P4 X-preload (96-383) ===
    if (bid < 48) {
        float* qs  = smem;            // [0,128)
        float* vs  = smem + 128;      // [128,256)
        float* sc  = smem + 256;      // [256,304)
        float* sp4 = smem + 304;      // [304,496)
        float* se  = smem + 496;      // [496,544)
        int i = bid;
        if (tid < 128) {
            qs[tid] = g_qkp[0][i * 256 + tid] + g_qkp[1][i * 256 + tid];
            vs[tid] = v[tid];
        }
        __syncthreads();
        int s = tid >> 6, u = tid & 63;        // 4 a-chunks(32) x 48 keys
        float ps = 0.f;
        if (u < 48) {
            const float4* k0 = (const float4*)&g_qkp[0][u * 256 + 128 + s * 32];
            const float4* k1 = (const float4*)&g_qkp[1][u * 256 + 128 + s * 32];
            const float *qq = &qs[s * 32], *vv = &vs[s * 32];
#pragma unroll
            for (int a4 = 0; a4 < 8; a4++) {
                float4 x0 = k0[a4], x1 = k1[a4];
                int a = a4 * 4;
                ps += vv[a + 0] * ftanh(qq[a + 0] + x0.x + x1.x);
                ps += vv[a + 1] * ftanh(qq[a + 1] + x0.y + x1.y);
                ps += vv[a + 2] * ftanh(qq[a + 2] + x0.z + x1.z);
                ps += vv[a + 3] * ftanh(qq[a + 3] + x0.w + x1.w);
            }
            sp4[s * 48 + u] = ps;
        }
        __syncthreads();
        if (tid < 48)
            sc[tid] = sp4[tid] + sp4[48 + tid] + sp4[96 + tid] + sp4[144 + tid];
        __syncthreads();
        float e = 0.f;
        if (tid < 48) {
            float mx = sc[0];
#pragma unroll 8
            for (int j = 1; j < 48; j++) mx = fmaxf(mx, sc[j]);
            e = __expf(sc[tid] - mx);
            se[tid] = e;
        }
        __syncthreads();
        if (tid < 48) {
            float sum = 0.f;
#pragma unroll 8
            for (int j = 0; j < 48; j++) sum += se[j];
            g_attn[i * 48 + tid] = e / sum;
        }
    } else if (bid < 96) {
        int o = (bid - 48) * 256 + tid;        // h init = root + b_rgcn
        g_h[o] = g_rootp[0][o] + g_rootp[1][o] + b_rgcn[tid];
    } else if (bid < 384) {
        // preload this block's P4 X-tile + speakers (inputs; no dependency)
        int ks = (bid >> 3) & 7, d0 = ks * 32;
        float* xs = smem;                      // [48][32]
        for (int idx = tid; idx < 1536; idx += 256) {
            int i = idx >> 5, dd = idx & 31;
            xs[idx] = X[i * 256 + d0 + dd];
        }
        if (tid < 48) ((int*)(smem + 2176))[tid] = speaker[tid];
    }
    gsync();

    // ===== P4: h += Z_t @ W_t, Z built inline ==============================
    // 384 blocks: 8 types x 8 ksplit(32) x 6 rowtiles(8).
    // Blocks 384-395: init out = b_gcn.
    if (bid < 384) {
        int t = bid & 7, ks = (bid >> 3) & 7, rt = bid >> 6;
        int tb   = (t >> 1) & 1;               // sp_j bit of this type
        int tsi  = t >> 2;                     // sp_i bit
        int dirb = t & 1;                      // direction bit
        int row0 = rt * 8, d0 = ks * 32;
        float* xs = smem;                      // [48][32]
        float* as = smem + 1536;               // [48][8]
        float* zs = smem + 1920;               // [8][32]
        int*   sp = (int*)(smem + 2176);       // [48]
        if (bid < 96) {                        // not preloaded during P2
            for (int idx = tid; idx < 1536; idx += 256) {
                int i = idx >> 5, dd = idx & 31;
                xs[idx] = X[i * 256 + d0 + dd];
            }
            if (tid < 48) sp[tid] = speaker[tid];
        }
        for (int idx = tid; idx < 384; idx += 256) {
            int i = idx >> 3, jj = idx & 7;
            as[idx] = g_attn[i * 48 + row0 + jj];
        }
        __syncthreads();

        // Z: 256 elements, 1/thread
        {
            int jj = tid >> 5, d = tid & 31;
            int j = row0 + jj;
            float acc = 0.f;
#pragma unroll 8
            for (int i = 0; i < 48; i++) {
                int dir = (i < j) ? 0 : 1;
                bool inc = (sp[i] == tsi) && (dir == dirb);
                acc += inc ? as[i * 8 + jj] * xs[i * 32 + d] : 0.f;
            }
            zs[jj * 32 + d] = acc;
        }
        __syncthreads();

        // GEMM: thread micro-tile 2 rows x 4 cols, K=32, float4 W loads
        int cq = (tid & 63) * 4, rg = tid >> 6;
        const float* W = Wrel + (size_t)c_etype[t] * 65536 + (size_t)d0 * 256 + cq;
        const float* z = &zs[rg * 2 * 32];
        float4 a0 = {0,0,0,0}, a1 = {0,0,0,0};
#pragma unroll 8
        for (int d = 0; d < 32; d++) {
            float4 w = *(const float4*)&W[(size_t)d * 256];
            float v0 = z[d], v1 = z[32 + d];
            a0.x = fmaf(v0, w.x, a0.x); a0.y = fmaf(v0, w.y, a0.y);
            a0.z = fmaf(v0, w.z, a0.z); a0.w = fmaf(v0, w.w, a0.w);
            a1.x = fmaf(v1, w.x, a1.x); a1.y = fmaf(v1, w.y, a1.y);
            a1.z = fmaf(v1, w.z, a1.z); a1.w = fmaf(v1, w.w, a1.w);
        }
        int lr = rg * 2;
        if (sp[row0 + lr + 0] == tb) {
            float* p = &g_h[(row0 + lr + 0) * 256 + cq];
            atomicAdd(p+0, a0.x); atomicAdd(p+1, a0.y);
            atomicAdd(p+2, a0.z); atomicAdd(p+3, a0.w);
        }
        if (sp[row0 + lr + 1] == tb) {
            float* p = &g_h[(row0 + lr + 1) * 256 + cq];
            atomicAdd(p+0, a1.x); atomicAdd(p+1, a1.y);
            atomicAdd(p+2, a1.z); atomicAdd(p+3, a1.w);
        }
    } else {
        int base = (bid - 384) * 1024;         // init out = bias (12 x 1024)
        float b = bg[tid];
#pragma unroll
        for (int k = 0; k < 4; k++)
            out[base + k * 256 + tid] = b;
    }
    gsync();

    // ===== P5: out += h @ W_self (k-split REDG)  +  broadcast T ============
    if (bid < 384) {
        // 48 rows x 2 colhalves(128) x 4 ksplit(64); inner ki splits 32.
        int rt = bid >> 3, cs = (bid >> 2) & 1, ks = bid & 3;
        float* hs  = smem;                     // [64]
        float* red = smem + 64;                // [128]
        if (tid < 64) hs[tid] = g_h[rt * 256 + ks * 64 + tid];
        __syncthreads();
        int cl = tid & 127, ki = tid >> 7;
        int c  = cs * 128 + cl;
        const float* Wb = Wself + (size_t)(ks * 64 + ki * 32) * 256 + c;
        const float* h0 = &hs[ki * 32];
        float a0 = 0.f;
#pragma unroll 8
        for (int d = 0; d < 32; d++)
            a0 = fmaf(h0[d], Wb[(size_t)d * 256], a0);
        if (ki == 1) red[cl] = a0;
        __syncthreads();
        if (ki == 0)
            atomicAdd(&out[rt * 256 + c], a0 + red[cl]);
    } else if (bid < 388) {
        // blocks 384..387: T k-chunk partial, scatter-added to all 48 rows
        int b = bid - 384;
        float* Ssc = smem;                     // [4][64]
        float* Sc  = smem + 256;               // [64]
        int dd = tid & 63, jg = tid >> 6;
        float s = 0.f;
#pragma unroll
        for (int j = jg * 12; j < jg * 12 + 12; j++)
            s += g_h[j * 256 + b * 64 + dd];
        Ssc[jg * 64 + dd] = s;
        __syncthreads();
        if (tid < 64) Sc[tid] = Ssc[tid] + Ssc[64 + tid] + Ssc[128 + tid] + Ssc[192 + tid];
        __syncthreads();
        float t = 0.f;
#pragma unroll 8
        for (int d = 0; d < 64; d++)
            t = fmaf(Sc[d], Wnbr[(size_t)(b * 64 + d) * 256 + tid], t);
#pragma unroll 8
        for (int j = 0; j < 48; j++)
            atomicAdd(&out[j * 256 + tid], t);
    }
}

extern "C" void kernel_launch(void* const* d_in, const int* in_sizes, int n_in,
                              void* d_out, int out_size) {
    const float* X      = (const float*)d_in[0];
    const int*   spk    = (const int*)  d_in[1];
    const float* Wq     = (const float*)d_in[2];
    const float* Wk     = (const float*)d_in[3];
    const float* v      = (const float*)d_in[4];
    const float* Wrel   = (const float*)d_in[5];
    const float* Wroot  = (const float*)d_in[6];
    const float* b_rgcn = (const float*)d_in[7];
    const float* Wnbr   = (const float*)d_in[8];
    const float* Wself  = (const float*)d_in[9];
    const float* b_gcn  = (const float*)d_in[10];
    float* out = (float*)d_out;

    fused<<<NB, 256>>>(X, spk, Wq, Wk, v, Wrel, Wroot, b_rgcn, Wnbr, Wself,
                       b_gcn, out);
}